// round 1
// baseline (speedup 1.0000x reference)
#include <cuda_runtime.h>
#include <math.h>

#define N_NODES 50000
#define N_EDGES 640000
#define DIM_IN  128
#define HC      128
#define DIM_OUT 32
#define HEADS   4
#define NEG_SLOPE 0.2f

// ---------------- scratch (device globals: no allocation allowed) ----------
__device__ float g_xl[(size_t)N_NODES * HC];     // 25.6 MB
__device__ float g_xr[(size_t)N_NODES * HC];     // 25.6 MB
__device__ int   g_cnt[N_NODES];
__device__ int   g_off[N_NODES + 1];
__device__ int   g_woff[N_NODES];
__device__ int   g_srcs[N_EDGES];

// ---------------- fused GEMM: xl = x@Wl, xr = x@Wr -------------------------
// 32 nodes per block, 256 threads. Thread = 4 consecutive cols x 8 nodes.
// cols 0..127 -> Wl/g_xl ; cols 128..255 -> Wr/g_xr
__global__ __launch_bounds__(256) void gemm_xlxr(const float* __restrict__ x,
                                                 const float* __restrict__ Wl,
                                                 const float* __restrict__ Wr) {
    __shared__ float xs[32][DIM_IN];
    const int t  = threadIdx.x;
    const int n0 = blockIdx.x * 32;

    // load x tile (zero-pad past N)
    for (int i = t; i < 32 * (DIM_IN / 4); i += 256) {
        int row = i / (DIM_IN / 4);
        int k4  = i % (DIM_IN / 4);
        int node = n0 + row;
        float4 v = make_float4(0.f, 0.f, 0.f, 0.f);
        if (node < N_NODES) v = ((const float4*)x)[(size_t)node * (DIM_IN / 4) + k4];
        ((float4*)&xs[row][0])[k4] = v;
    }
    __syncthreads();

    const int cg = t & 63;          // col group 0..63
    const int c0 = cg * 4;          // 0..252
    const int ns = t >> 6;          // 0..3 -> nodes ns*8..ns*8+7
    const float* Wb = (c0 < HC) ? (Wl + c0) : (Wr + (c0 - HC));

    float acc[8][4];
#pragma unroll
    for (int n = 0; n < 8; n++) { acc[n][0] = acc[n][1] = acc[n][2] = acc[n][3] = 0.f; }

#pragma unroll 4
    for (int k = 0; k < DIM_IN; k++) {
        float4 w = *(const float4*)(Wb + (size_t)k * HC);
#pragma unroll
        for (int n = 0; n < 8; n++) {
            float xv = xs[ns * 8 + n][k];
            acc[n][0] += xv * w.x;
            acc[n][1] += xv * w.y;
            acc[n][2] += xv * w.z;
            acc[n][3] += xv * w.w;
        }
    }

    float* outp = (c0 < HC) ? g_xl : g_xr;
    const int cc = (c0 < HC) ? c0 : (c0 - HC);
#pragma unroll
    for (int n = 0; n < 8; n++) {
        int node = n0 + ns * 8 + n;
        if (node < N_NODES) {
            *(float4*)(outp + (size_t)node * HC + cc) =
                make_float4(acc[n][0], acc[n][1], acc[n][2], acc[n][3]);
        }
    }
}

// ---------------- CSR build -------------------------------------------------
__global__ void zero_cnt_kernel() {
    int i = blockIdx.x * blockDim.x + threadIdx.x;
    if (i < N_NODES) g_cnt[i] = 0;
}

__global__ void hist_kernel(const int* __restrict__ dst) {
    int e = blockIdx.x * blockDim.x + threadIdx.x;
    if (e < N_EDGES) atomicAdd(&g_cnt[dst[e]], 1);
}

// single-block exclusive scan of g_cnt -> g_off / g_woff
__global__ __launch_bounds__(1024) void scan_kernel() {
    __shared__ int ssum[1024];
    const int t = threadIdx.x;
    const int CH = (N_NODES + 1023) / 1024;   // 49
    const int base = t * CH;

    int s = 0;
    for (int j = 0; j < CH; j++) {
        int i = base + j;
        if (i < N_NODES) s += g_cnt[i];
    }
    ssum[t] = s;
    __syncthreads();
    for (int d = 1; d < 1024; d <<= 1) {
        int v = (t >= d) ? ssum[t - d] : 0;
        __syncthreads();
        ssum[t] += v;
        __syncthreads();
    }
    int run = (t == 0) ? 0 : ssum[t - 1];
    for (int j = 0; j < CH; j++) {
        int i = base + j;
        if (i < N_NODES) {
            int c = g_cnt[i];
            g_off[i]  = run;
            g_woff[i] = run;
            run += c;
        }
    }
    if (t == 1023) g_off[N_NODES] = run;
}

__global__ void scatter_kernel(const int* __restrict__ src, const int* __restrict__ dst) {
    int e = blockIdx.x * blockDim.x + threadIdx.x;
    if (e < N_EDGES) {
        int d = dst[e];
        int p = atomicAdd(&g_woff[d], 1);
        g_srcs[p] = src[e];
    }
}

// ---------------- per-node fused attention + aggregation + projection ------
// one warp per node, 8 nodes per 256-thread block.
// lane l owns feature slots 4l..4l+3 (head h = l/8).
__device__ __forceinline__ float lrelu(float v) {
    return v > 0.f ? v : NEG_SLOPE * v;
}

__global__ __launch_bounds__(256) void node_kernel(const float* __restrict__ att,
                                                   const float* __restrict__ bias,
                                                   const float* __restrict__ Wp,
                                                   const float* __restrict__ bp,
                                                   float* __restrict__ out) {
    __shared__ float Wps[HC * DIM_OUT];   // 16 KB, [k][o]
    __shared__ float sbuf[8][HC];         // 4 KB per-warp scratch

    const int t = threadIdx.x;
    const int w = t >> 5;
    const int l = t & 31;

    for (int i = t; i < HC * DIM_OUT / 4; i += 256)
        ((float4*)Wps)[i] = ((const float4*)Wp)[i];
    __syncthreads();

    const int node = blockIdx.x * 8 + w;
    if (node >= N_NODES) return;

    const float4 xr4 = *(const float4*)(g_xr + (size_t)node * HC + l * 4);
    const float4 a4  = *(const float4*)(att + l * 4);

    const int e0 = g_off[node];
    const int e1 = g_off[node + 1];

    float m = -1e30f, denom = 0.f;
    float4 acc = make_float4(0.f, 0.f, 0.f, 0.f);

    // software pipeline: src two-ahead, xl one-ahead
    int s_e  = (e0 < e1)     ? __ldg(&g_srcs[e0])     : 0;
    int s_e1 = (e0 + 1 < e1) ? __ldg(&g_srcs[e0 + 1]) : 0;
    float4 xl_e = make_float4(0.f, 0.f, 0.f, 0.f);
    if (e0 < e1) xl_e = *(const float4*)(g_xl + (size_t)s_e * HC + l * 4);

    for (int e = e0; e < e1; e++) {
        int s_e2 = (e + 2 < e1) ? __ldg(&g_srcs[e + 2]) : 0;
        float4 xl_n = make_float4(0.f, 0.f, 0.f, 0.f);
        if (e + 1 < e1) xl_n = *(const float4*)(g_xl + (size_t)s_e1 * HC + l * 4);

        // logit partial for this lane's head slice
        float p = a4.x * lrelu(xl_e.x + xr4.x)
                + a4.y * lrelu(xl_e.y + xr4.y)
                + a4.z * lrelu(xl_e.z + xr4.z)
                + a4.w * lrelu(xl_e.w + xr4.w);
        // reduce within 8-lane group (same head)
        p += __shfl_xor_sync(0xffffffffu, p, 4);
        p += __shfl_xor_sync(0xffffffffu, p, 2);
        p += __shfl_xor_sync(0xffffffffu, p, 1);

        // online softmax update
        float mn    = fmaxf(m, p);
        float scale = __expf(m - mn);
        float ev    = __expf(p - mn);
        denom = denom * scale + ev;
        acc.x = acc.x * scale + xl_e.x * ev;
        acc.y = acc.y * scale + xl_e.y * ev;
        acc.z = acc.z * scale + xl_e.z * ev;
        acc.w = acc.w * scale + xl_e.w * ev;
        m = mn;

        s_e = s_e1; s_e1 = s_e2; xl_e = xl_n;
    }

    const float inv = 1.f / (denom + 1e-16f);
    const float4 b4 = *(const float4*)(bias + l * 4);
    sbuf[w][4 * l + 0] = acc.x * inv + b4.x;
    sbuf[w][4 * l + 1] = acc.y * inv + b4.y;
    sbuf[w][4 * l + 2] = acc.z * inv + b4.z;
    sbuf[w][4 * l + 3] = acc.w * inv + b4.w;
    __syncwarp();

    // projection: lane l computes output column l
    float r = bp[l];
#pragma unroll 8
    for (int k = 0; k < HC; k++)
        r += sbuf[w][k] * Wps[k * DIM_OUT + l];
    out[(size_t)node * DIM_OUT + l] = r;
}

// ---------------- launch ----------------------------------------------------
extern "C" void kernel_launch(void* const* d_in, const int* in_sizes, int n_in,
                              void* d_out, int out_size) {
    const float* x    = (const float*)d_in[0];
    const int*   ei   = (const int*)d_in[1];
    const float* Wl   = (const float*)d_in[2];
    const float* Wr   = (const float*)d_in[3];
    const float* att  = (const float*)d_in[4];
    const float* bias = (const float*)d_in[5];
    const float* Wp   = (const float*)d_in[6];
    const float* bp   = (const float*)d_in[7];
    const int* src = ei;
    const int* dst = ei + N_EDGES;

    gemm_xlxr<<<(N_NODES + 31) / 32, 256>>>(x, Wl, Wr);
    zero_cnt_kernel<<<(N_NODES + 255) / 256, 256>>>();
    hist_kernel<<<(N_EDGES + 255) / 256, 256>>>(dst);
    scan_kernel<<<1, 1024>>>();
    scatter_kernel<<<(N_EDGES + 255) / 256, 256>>>(src, dst);
    node_kernel<<<(N_NODES + 7) / 8, 256>>>(att, bias, Wp, bp, (float*)d_out);
}

// round 2
// speedup vs baseline: 1.3734x; 1.3734x over previous
#include <cuda_runtime.h>
#include <math.h>

#define N_NODES 50000
#define N_EDGES 640000
#define DIM_IN  128
#define HC      128
#define DIM_OUT 32
#define HEADS   4
#define NEG_SLOPE 0.2f

#define SCAN_CHUNK 1024
#define SCAN_NBLK  ((N_NODES + SCAN_CHUNK - 1) / SCAN_CHUNK)   // 49

// ---------------- scratch (device globals: no allocation allowed) ----------
__device__ float g_xl[(size_t)N_NODES * HC];     // 25.6 MB
__device__ float g_xr[(size_t)N_NODES * HC];     // 25.6 MB
__device__ int   g_cnt[N_NODES];
__device__ int   g_off[N_NODES + 1];
__device__ int   g_woff[N_NODES];
__device__ int   g_srcs[N_EDGES];
__device__ int   g_blocksum[SCAN_NBLK];

// ---------------- fused GEMM: xl = x@Wl, xr = x@Wr -------------------------
__global__ __launch_bounds__(256) void gemm_xlxr(const float* __restrict__ x,
                                                 const float* __restrict__ Wl,
                                                 const float* __restrict__ Wr) {
    __shared__ float xs[32][DIM_IN];
    const int t  = threadIdx.x;
    const int n0 = blockIdx.x * 32;

    for (int i = t; i < 32 * (DIM_IN / 4); i += 256) {
        int row = i / (DIM_IN / 4);
        int k4  = i % (DIM_IN / 4);
        int node = n0 + row;
        float4 v = make_float4(0.f, 0.f, 0.f, 0.f);
        if (node < N_NODES) v = ((const float4*)x)[(size_t)node * (DIM_IN / 4) + k4];
        ((float4*)&xs[row][0])[k4] = v;
    }
    __syncthreads();

    const int cg = t & 63;
    const int c0 = cg * 4;
    const int ns = t >> 6;
    const float* Wb = (c0 < HC) ? (Wl + c0) : (Wr + (c0 - HC));

    float acc[8][4];
#pragma unroll
    for (int n = 0; n < 8; n++) { acc[n][0] = acc[n][1] = acc[n][2] = acc[n][3] = 0.f; }

#pragma unroll 4
    for (int k = 0; k < DIM_IN; k++) {
        float4 w = *(const float4*)(Wb + (size_t)k * HC);
#pragma unroll
        for (int n = 0; n < 8; n++) {
            float xv = xs[ns * 8 + n][k];
            acc[n][0] += xv * w.x;
            acc[n][1] += xv * w.y;
            acc[n][2] += xv * w.z;
            acc[n][3] += xv * w.w;
        }
    }

    float* outp = (c0 < HC) ? g_xl : g_xr;
    const int cc = (c0 < HC) ? c0 : (c0 - HC);
#pragma unroll
    for (int n = 0; n < 8; n++) {
        int node = n0 + ns * 8 + n;
        if (node < N_NODES) {
            *(float4*)(outp + (size_t)node * HC + cc) =
                make_float4(acc[n][0], acc[n][1], acc[n][2], acc[n][3]);
        }
    }
}

// ---------------- CSR build -------------------------------------------------
__global__ void zero_cnt_kernel() {
    int i = blockIdx.x * blockDim.x + threadIdx.x;
    if (i < N_NODES) g_cnt[i] = 0;
}

__global__ void hist_kernel(const int* __restrict__ dst) {
    int e = blockIdx.x * blockDim.x + threadIdx.x;
    if (e < N_EDGES) atomicAdd(&g_cnt[dst[e]], 1);
}

// Hierarchical scan, stage A: per-block exclusive scan of 1024 elems,
// local-exclusive values -> g_off, block total -> g_blocksum.
__global__ __launch_bounds__(256) void scanA_kernel() {
    __shared__ int wsum[8];
    const int t = threadIdx.x;
    const int i0 = blockIdx.x * SCAN_CHUNK + t * 4;

    int4 v = make_int4(0, 0, 0, 0);
    if (i0 < N_NODES) v = *(const int4*)(g_cnt + i0);   // N_NODES % 4 == 0

    int e1 = v.x;
    int e2 = e1 + v.y;
    int e3 = e2 + v.z;
    int s  = e3 + v.w;

    // inclusive warp scan of s
    int incl = s;
#pragma unroll
    for (int d = 1; d < 32; d <<= 1) {
        int u = __shfl_up_sync(0xffffffffu, incl, d);
        if ((t & 31) >= d) incl += u;
    }
    if ((t & 31) == 31) wsum[t >> 5] = incl;
    __syncthreads();

    int wbase = 0;
    if (t < 8) {
        int ws = wsum[t];
        int wincl = ws;
#pragma unroll
        for (int d = 1; d < 8; d <<= 1) {
            int u = __shfl_up_sync(0x000000ffu, wincl, d);
            if (t >= d) wincl += u;
        }
        wsum[t] = wincl - ws;     // exclusive
        if (t == 7 && blockIdx.x < SCAN_NBLK) g_blocksum[blockIdx.x] = wincl;
    }
    __syncthreads();
    wbase = wsum[t >> 5];

    const int base = wbase + (incl - s);   // exclusive prefix for this thread
    if (i0 < N_NODES) {
        *(int4*)(g_off + i0) = make_int4(base, base + e1, base + e2, base + e3);
    }
}

// Stage C: add block bases, mirror to g_woff, write sentinel.
__global__ __launch_bounds__(256) void scanC_kernel() {
    __shared__ int bs[SCAN_NBLK];
    const int t = threadIdx.x;
    if (t < SCAN_NBLK) bs[t] = g_blocksum[t];
    __syncthreads();

    int base = 0;
#pragma unroll 8
    for (int j = 0; j < SCAN_NBLK; j++)
        if (j < blockIdx.x) base += bs[j];

    const int i0 = blockIdx.x * SCAN_CHUNK + t * 4;
    if (i0 < N_NODES) {
        int4 v = *(const int4*)(g_off + i0);
        v.x += base; v.y += base; v.z += base; v.w += base;
        *(int4*)(g_off + i0)  = v;
        *(int4*)(g_woff + i0) = v;
    }
    if (blockIdx.x == 0 && t == 0) g_off[N_NODES] = N_EDGES;  // all dst in [0,N)
}

__global__ void scatter_kernel(const int* __restrict__ src, const int* __restrict__ dst) {
    int e = blockIdx.x * blockDim.x + threadIdx.x;
    if (e < N_EDGES) {
        int d = dst[e];
        int p = atomicAdd(&g_woff[d], 1);
        g_srcs[p] = src[e];
    }
}

// ---------------- per-node fused attention + aggregation + projection ------
__device__ __forceinline__ float lrelu(float v) {
    return v > 0.f ? v : NEG_SLOPE * v;
}

__global__ __launch_bounds__(256) void node_kernel(const float* __restrict__ att,
                                                   const float* __restrict__ bias,
                                                   const float* __restrict__ Wp,
                                                   const float* __restrict__ bp,
                                                   float* __restrict__ out) {
    __shared__ float Wps[HC * DIM_OUT];   // 16 KB, [k][o]
    __shared__ float sbuf[8][HC];

    const int t = threadIdx.x;
    const int w = t >> 5;
    const int l = t & 31;

    for (int i = t; i < HC * DIM_OUT / 4; i += 256)
        ((float4*)Wps)[i] = ((const float4*)Wp)[i];
    __syncthreads();

    const int node = blockIdx.x * 8 + w;
    if (node >= N_NODES) return;

    const float4 xr4 = *(const float4*)(g_xr + (size_t)node * HC + l * 4);
    const float4 a4  = *(const float4*)(att + l * 4);

    const int e0 = g_off[node];
    const int e1 = g_off[node + 1];

    float m = -1e30f, denom = 0.f;
    float4 acc = make_float4(0.f, 0.f, 0.f, 0.f);

    int s_e  = (e0 < e1)     ? __ldg(&g_srcs[e0])     : 0;
    int s_e1 = (e0 + 1 < e1) ? __ldg(&g_srcs[e0 + 1]) : 0;
    float4 xl_e = make_float4(0.f, 0.f, 0.f, 0.f);
    if (e0 < e1) xl_e = *(const float4*)(g_xl + (size_t)s_e * HC + l * 4);

    for (int e = e0; e < e1; e++) {
        int s_e2 = (e + 2 < e1) ? __ldg(&g_srcs[e + 2]) : 0;
        float4 xl_n = make_float4(0.f, 0.f, 0.f, 0.f);
        if (e + 1 < e1) xl_n = *(const float4*)(g_xl + (size_t)s_e1 * HC + l * 4);

        float p = a4.x * lrelu(xl_e.x + xr4.x)
                + a4.y * lrelu(xl_e.y + xr4.y)
                + a4.z * lrelu(xl_e.z + xr4.z)
                + a4.w * lrelu(xl_e.w + xr4.w);
        p += __shfl_xor_sync(0xffffffffu, p, 4);
        p += __shfl_xor_sync(0xffffffffu, p, 2);
        p += __shfl_xor_sync(0xffffffffu, p, 1);

        float mn    = fmaxf(m, p);
        float scale = __expf(m - mn);
        float ev    = __expf(p - mn);
        denom = denom * scale + ev;
        acc.x = acc.x * scale + xl_e.x * ev;
        acc.y = acc.y * scale + xl_e.y * ev;
        acc.z = acc.z * scale + xl_e.z * ev;
        acc.w = acc.w * scale + xl_e.w * ev;
        m = mn;

        s_e = s_e1; s_e1 = s_e2; xl_e = xl_n;
    }

    const float inv = 1.f / (denom + 1e-16f);
    const float4 b4 = *(const float4*)(bias + l * 4);
    sbuf[w][4 * l + 0] = acc.x * inv + b4.x;
    sbuf[w][4 * l + 1] = acc.y * inv + b4.y;
    sbuf[w][4 * l + 2] = acc.z * inv + b4.z;
    sbuf[w][4 * l + 3] = acc.w * inv + b4.w;
    __syncwarp();

    float r = bp[l];
#pragma unroll 8
    for (int k = 0; k < HC; k++)
        r += sbuf[w][k] * Wps[k * DIM_OUT + l];
    out[(size_t)node * DIM_OUT + l] = r;
}

// ---------------- launch ----------------------------------------------------
extern "C" void kernel_launch(void* const* d_in, const int* in_sizes, int n_in,
                              void* d_out, int out_size) {
    const float* x    = (const float*)d_in[0];
    const int*   ei   = (const int*)d_in[1];
    const float* Wl   = (const float*)d_in[2];
    const float* Wr   = (const float*)d_in[3];
    const float* att  = (const float*)d_in[4];
    const float* bias = (const float*)d_in[5];
    const float* Wp   = (const float*)d_in[6];
    const float* bp   = (const float*)d_in[7];
    const int* src = ei;
    const int* dst = ei + N_EDGES;

    gemm_xlxr<<<(N_NODES + 31) / 32, 256>>>(x, Wl, Wr);
    zero_cnt_kernel<<<(N_NODES + 255) / 256, 256>>>();
    hist_kernel<<<(N_EDGES + 255) / 256, 256>>>(dst);
    scanA_kernel<<<SCAN_NBLK, 256>>>();
    scanC_kernel<<<SCAN_NBLK, 256>>>();
    scatter_kernel<<<(N_EDGES + 255) / 256, 256>>>(src, dst);
    node_kernel<<<(N_NODES + 7) / 8, 256>>>(att, bias, Wp, bp, (float*)d_out);
}

// round 3
// speedup vs baseline: 1.5448x; 1.1248x over previous
#include <cuda_runtime.h>
#include <math.h>

#define N_NODES 50000
#define N_EDGES 640000
#define DIM_IN  128
#define HC      128
#define DIM_OUT 32
#define HEADS   4
#define NEG_SLOPE 0.2f

#define SCAN_CHUNK 1024
#define SCAN_NBLK  ((N_NODES + SCAN_CHUNK - 1) / SCAN_CHUNK)   // 49

typedef unsigned long long u64;

// ---------------- f32x2 helpers (Blackwell packed fp32, PTX-only) ----------
__device__ __forceinline__ u64 pack2(float lo, float hi) {
    u64 r; asm("mov.b64 %0, {%1, %2};" : "=l"(r) : "f"(lo), "f"(hi)); return r;
}
__device__ __forceinline__ void ffma2(u64& d, u64 a, u64 b) {
    asm("fma.rn.f32x2 %0, %1, %2, %3;" : "=l"(d) : "l"(a), "l"(b), "l"(d));
}
__device__ __forceinline__ float2 unpack2(u64 v) {
    float2 f; asm("mov.b64 {%0, %1}, %2;" : "=f"(f.x), "=f"(f.y) : "l"(v)); return f;
}

// ---------------- scratch (device globals: no allocation allowed) ----------
__device__ float g_xl[(size_t)N_NODES * HC];     // 25.6 MB
__device__ float g_xr[(size_t)N_NODES * HC];     // 25.6 MB
__device__ int   g_cnt[N_NODES];
__device__ int   g_off[N_NODES + 1];
__device__ int   g_woff[N_NODES];
__device__ int   g_srcs[N_EDGES];
__device__ int   g_blocksum[SCAN_NBLK];

// ---------------- fused GEMM (f32x2) + dst histogram ------------------------
// 32 nodes/block, 256 threads. thread = 4 cols x 8 nodes (4 node-pairs).
// cols 0..127 -> Wl/g_xl ; 128..255 -> Wr/g_xr.
__global__ __launch_bounds__(256) void gemm_xlxr(const float* __restrict__ x,
                                                 const float* __restrict__ Wl,
                                                 const float* __restrict__ Wr,
                                                 const int* __restrict__ dst) {
    __shared__ float xs[DIM_IN][34];   // [k][node], pad even -> 8B-aligned rows
    const int t  = threadIdx.x;
    const int n0 = blockIdx.x * 32;

    // histogram slice (fire-and-forget atomics, hidden under FMA mainloop)
    for (int e = blockIdx.x * 256 + t; e < N_EDGES; e += gridDim.x * 256)
        atomicAdd(&g_cnt[dst[e]], 1);

    // load x tile, transposed into xs[k][node]
    for (int i = t; i < 32 * (DIM_IN / 4); i += 256) {
        int node = i >> 5;
        int k4   = i & 31;
        int gn   = n0 + node;
        float4 v = make_float4(0.f, 0.f, 0.f, 0.f);
        if (gn < N_NODES) v = ((const float4*)x)[(size_t)gn * (DIM_IN / 4) + k4];
        xs[4 * k4 + 0][node] = v.x;
        xs[4 * k4 + 1][node] = v.y;
        xs[4 * k4 + 2][node] = v.z;
        xs[4 * k4 + 3][node] = v.w;
    }
    __syncthreads();

    const int cg = t & 63;
    const int c0 = cg * 4;
    const int ns = t >> 6;          // warp-uniform
    const float* Wb = (c0 < HC) ? (Wl + c0) : (Wr + (c0 - HC));

    u64 acc2[4][4];
#pragma unroll
    for (int p = 0; p < 4; p++)
#pragma unroll
        for (int c = 0; c < 4; c++) acc2[p][c] = pack2(0.f, 0.f);

#pragma unroll 2
    for (int k = 0; k < DIM_IN; k++) {
        float4 w = *(const float4*)(Wb + (size_t)k * HC);
        u64 w0 = pack2(w.x, w.x);
        u64 w1 = pack2(w.y, w.y);
        u64 w2 = pack2(w.z, w.z);
        u64 w3 = pack2(w.w, w.w);
        const u64* xp = (const u64*)&xs[k][ns * 8];  // broadcast within warp
        u64 v0 = xp[0], v1 = xp[1], v2 = xp[2], v3 = xp[3];
        ffma2(acc2[0][0], v0, w0); ffma2(acc2[0][1], v0, w1);
        ffma2(acc2[0][2], v0, w2); ffma2(acc2[0][3], v0, w3);
        ffma2(acc2[1][0], v1, w0); ffma2(acc2[1][1], v1, w1);
        ffma2(acc2[1][2], v1, w2); ffma2(acc2[1][3], v1, w3);
        ffma2(acc2[2][0], v2, w0); ffma2(acc2[2][1], v2, w1);
        ffma2(acc2[2][2], v2, w2); ffma2(acc2[2][3], v2, w3);
        ffma2(acc2[3][0], v3, w0); ffma2(acc2[3][1], v3, w1);
        ffma2(acc2[3][2], v3, w2); ffma2(acc2[3][3], v3, w3);
    }

    float* outp = (c0 < HC) ? g_xl : g_xr;
    const int cc = (c0 < HC) ? c0 : (c0 - HC);
#pragma unroll
    for (int p = 0; p < 4; p++) {
        int nA = n0 + ns * 8 + 2 * p;
        int nB = nA + 1;
        float2 q0 = unpack2(acc2[p][0]);
        float2 q1 = unpack2(acc2[p][1]);
        float2 q2 = unpack2(acc2[p][2]);
        float2 q3 = unpack2(acc2[p][3]);
        if (nA < N_NODES)
            *(float4*)(outp + (size_t)nA * HC + cc) = make_float4(q0.x, q1.x, q2.x, q3.x);
        if (nB < N_NODES)
            *(float4*)(outp + (size_t)nB * HC + cc) = make_float4(q0.y, q1.y, q2.y, q3.y);
    }
}

// ---------------- CSR build -------------------------------------------------
__global__ void zero_cnt_kernel() {
    int i = blockIdx.x * blockDim.x + threadIdx.x;
    if (i < N_NODES) g_cnt[i] = 0;
}

__global__ __launch_bounds__(256) void scanA_kernel() {
    __shared__ int wsum[8];
    const int t = threadIdx.x;
    const int i0 = blockIdx.x * SCAN_CHUNK + t * 4;

    int4 v = make_int4(0, 0, 0, 0);
    if (i0 < N_NODES) v = *(const int4*)(g_cnt + i0);

    int e1 = v.x;
    int e2 = e1 + v.y;
    int e3 = e2 + v.z;
    int s  = e3 + v.w;

    int incl = s;
#pragma unroll
    for (int d = 1; d < 32; d <<= 1) {
        int u = __shfl_up_sync(0xffffffffu, incl, d);
        if ((t & 31) >= d) incl += u;
    }
    if ((t & 31) == 31) wsum[t >> 5] = incl;
    __syncthreads();

    if (t < 8) {
        int ws = wsum[t];
        int wincl = ws;
#pragma unroll
        for (int d = 1; d < 8; d <<= 1) {
            int u = __shfl_up_sync(0x000000ffu, wincl, d);
            if (t >= d) wincl += u;
        }
        wsum[t] = wincl - ws;
        if (t == 7) g_blocksum[blockIdx.x] = wincl;
    }
    __syncthreads();
    int wbase = wsum[t >> 5];

    const int base = wbase + (incl - s);
    if (i0 < N_NODES)
        *(int4*)(g_off + i0) = make_int4(base, base + e1, base + e2, base + e3);
}

__global__ __launch_bounds__(256) void scanC_kernel() {
    __shared__ int bs[SCAN_NBLK];
    const int t = threadIdx.x;
    if (t < SCAN_NBLK) bs[t] = g_blocksum[t];
    __syncthreads();

    int base = 0;
#pragma unroll 8
    for (int j = 0; j < SCAN_NBLK; j++)
        if (j < blockIdx.x) base += bs[j];

    const int i0 = blockIdx.x * SCAN_CHUNK + t * 4;
    if (i0 < N_NODES) {
        int4 v = *(const int4*)(g_off + i0);
        v.x += base; v.y += base; v.z += base; v.w += base;
        *(int4*)(g_off + i0)  = v;
        *(int4*)(g_woff + i0) = v;
    }
    if (blockIdx.x == 0 && t == 0) g_off[N_NODES] = N_EDGES;
}

__global__ void scatter_kernel(const int* __restrict__ src, const int* __restrict__ dst) {
    int e = blockIdx.x * blockDim.x + threadIdx.x;
    if (e < N_EDGES) {
        int d = dst[e];
        int p = atomicAdd(&g_woff[d], 1);
        g_srcs[p] = src[e];
    }
}

// ---------------- per-node fused attention + aggregation + projection ------
// 256 threads, 8 warps, 4 nodes per warp -> 32 nodes/block.
// lane l owns feature slots 4l..4l+3 (head = l/8).
__device__ __forceinline__ float lrelu(float v) {
    return v > 0.f ? v : NEG_SLOPE * v;
}

__global__ __launch_bounds__(256) void node_kernel(const float* __restrict__ att,
                                                   const float* __restrict__ bias,
                                                   const float* __restrict__ Wp,
                                                   const float* __restrict__ bp,
                                                   float* __restrict__ out) {
    __shared__ float Wpt[DIM_OUT][130];   // transposed [o][k], pad 130 (8B-aligned, conflict-free LDS.64)
    __shared__ float sbuf[8][HC];

    const int t = threadIdx.x;
    const int w = t >> 5;
    const int l = t & 31;

    // load & transpose Wp[k][o] -> Wpt[o][k]
    for (int i = t; i < HC * DIM_OUT / 4; i += 256) {
        float4 v = ((const float4*)Wp)[i];
        int k = i >> 3;
        int o = (i & 7) * 4;
        Wpt[o + 0][k] = v.x;
        Wpt[o + 1][k] = v.y;
        Wpt[o + 2][k] = v.z;
        Wpt[o + 3][k] = v.w;
    }
    __syncthreads();

    const float4 a4  = *(const float4*)(att + l * 4);
    const float4 b4  = *(const float4*)(bias + l * 4);
    const float  bpl = bp[l];
    const int wg = blockIdx.x * 8 + w;

    for (int nn = 0; nn < 4; nn++) {
        const int node = wg * 4 + nn;
        if (node >= N_NODES) break;   // consecutive nodes; no block-wide sync below

        const float4 xr4 = *(const float4*)(g_xr + (size_t)node * HC + l * 4);
        const int e0 = g_off[node];
        const int e1 = g_off[node + 1];

        float denom = 0.f;
        float4 acc = make_float4(0.f, 0.f, 0.f, 0.f);

        for (int base = e0; base < e1; base += 32) {
            const int nE = min(32, e1 - base);
            int sv = 0;
            if (l < nE) sv = g_srcs[base + l];   // one coalesced load per 32 edges

            for (int j = 0; j < nE; j += 2) {
                const int s0 = __shfl_sync(0xffffffffu, sv, j);
                const int s1 = __shfl_sync(0xffffffffu, sv, (j + 1) & 31);
                const bool h1 = (j + 1) < nE;

                const float4 x0 = *(const float4*)(g_xl + (size_t)s0 * HC + l * 4);
                float4 x1 = make_float4(0.f, 0.f, 0.f, 0.f);
                if (h1) x1 = *(const float4*)(g_xl + (size_t)s1 * HC + l * 4);

                float p0 = a4.x * lrelu(x0.x + xr4.x)
                         + a4.y * lrelu(x0.y + xr4.y)
                         + a4.z * lrelu(x0.z + xr4.z)
                         + a4.w * lrelu(x0.w + xr4.w);
                float p1 = a4.x * lrelu(x1.x + xr4.x)
                         + a4.y * lrelu(x1.y + xr4.y)
                         + a4.z * lrelu(x1.z + xr4.z)
                         + a4.w * lrelu(x1.w + xr4.w);

                // per-head 8-lane reductions, two chains interleaved for ILP
                p0 += __shfl_xor_sync(0xffffffffu, p0, 4);
                p1 += __shfl_xor_sync(0xffffffffu, p1, 4);
                p0 += __shfl_xor_sync(0xffffffffu, p0, 2);
                p1 += __shfl_xor_sync(0xffffffffu, p1, 2);
                p0 += __shfl_xor_sync(0xffffffffu, p0, 1);
                p1 += __shfl_xor_sync(0xffffffffu, p1, 1);

                // shift-free softmax terms (any per-node shift cancels; logits O(1))
                const float ev0 = __expf(p0);
                const float ev1 = h1 ? __expf(p1) : 0.f;
                denom += ev0 + ev1;
                acc.x += x0.x * ev0 + x1.x * ev1;
                acc.y += x0.y * ev0 + x1.y * ev1;
                acc.z += x0.z * ev0 + x1.z * ev1;
                acc.w += x0.w * ev0 + x1.w * ev1;
            }
        }

        const float inv = 1.f / (denom + 1e-16f);
        sbuf[w][4 * l + 0] = acc.x * inv + b4.x;
        sbuf[w][4 * l + 1] = acc.y * inv + b4.y;
        sbuf[w][4 * l + 2] = acc.z * inv + b4.z;
        sbuf[w][4 * l + 3] = acc.w * inv + b4.w;
        __syncwarp();

        // projection: lane l -> output col l, f32x2 over k-pairs
        const u64* sp = (const u64*)&sbuf[w][0];
        const u64* wp = (const u64*)&Wpt[l][0];
        u64 r2 = pack2(bpl, 0.f);
#pragma unroll 8
        for (int k2 = 0; k2 < HC / 2; k2++) ffma2(r2, sp[k2], wp[k2]);
        float2 rr = unpack2(r2);
        out[(size_t)node * DIM_OUT + l] = rr.x + rr.y;
        __syncwarp();   // protect sbuf[w] before next node overwrites
    }
}

// ---------------- launch ----------------------------------------------------
extern "C" void kernel_launch(void* const* d_in, const int* in_sizes, int n_in,
                              void* d_out, int out_size) {
    const float* x    = (const float*)d_in[0];
    const int*   ei   = (const int*)d_in[1];
    const float* Wl   = (const float*)d_in[2];
    const float* Wr   = (const float*)d_in[3];
    const float* att  = (const float*)d_in[4];
    const float* bias = (const float*)d_in[5];
    const float* Wp   = (const float*)d_in[6];
    const float* bp   = (const float*)d_in[7];
    const int* src = ei;
    const int* dst = ei + N_EDGES;

    zero_cnt_kernel<<<(N_NODES + 255) / 256, 256>>>();
    gemm_xlxr<<<(N_NODES + 31) / 32, 256>>>(x, Wl, Wr, dst);   // + hidden histogram
    scanA_kernel<<<SCAN_NBLK, 256>>>();
    scanC_kernel<<<SCAN_NBLK, 256>>>();
    scatter_kernel<<<(N_EDGES + 255) / 256, 256>>>(src, dst);
    node_kernel<<<(N_NODES + 31) / 32, 256>>>(att, bias, Wp, bp, (float*)d_out);
}

// round 5
// speedup vs baseline: 1.6014x; 1.0366x over previous
#include <cuda_runtime.h>
#include <cuda_bf16.h>
#include <math.h>

#define N_NODES 50000
#define N_EDGES 640000
#define DIM_IN  128
#define HC      128
#define DIM_OUT 32
#define HEADS   4
#define NEG_SLOPE 0.2f

#define SCAN_CHUNK 1024
#define SCAN_NBLK  ((N_NODES + SCAN_CHUNK - 1) / SCAN_CHUNK)   // 49

#define M_TILE   128
#define N_MTILES ((N_NODES + M_TILE - 1) / M_TILE)             // 391

typedef unsigned long long u64;
typedef unsigned int u32;

// ---------------- f32x2 helpers (node-kernel projection) --------------------
__device__ __forceinline__ u64 pack2(float lo, float hi) {
    u64 r; asm("mov.b64 %0, {%1, %2};" : "=l"(r) : "f"(lo), "f"(hi)); return r;
}
__device__ __forceinline__ void ffma2(u64& d, u64 a, u64 b) {
    asm("fma.rn.f32x2 %0, %1, %2, %3;" : "=l"(d) : "l"(a), "l"(b), "l"(d));
}
__device__ __forceinline__ float2 unpack2(u64 v) {
    float2 f; asm("mov.b64 {%0, %1}, %2;" : "=f"(f.x), "=f"(f.y) : "l"(v)); return f;
}

// ---------------- warp-MMA helpers (compute_103-safe: sm_80-era ops) --------
__device__ __forceinline__ u32 smem_u32(const void* p) {
    u32 a;
    asm("{ .reg .u64 tmp; cvta.to.shared.u64 tmp, %1; cvt.u32.u64 %0, tmp; }"
        : "=r"(a) : "l"(p));
    return a;
}
__device__ __forceinline__ void ldsm_x4(u32& r0, u32& r1, u32& r2, u32& r3, u32 addr) {
    asm volatile("ldmatrix.sync.aligned.m8n8.x4.shared.b16 {%0,%1,%2,%3}, [%4];"
                 : "=r"(r0), "=r"(r1), "=r"(r2), "=r"(r3) : "r"(addr));
}
__device__ __forceinline__ void mma_bf16(float* d, const u32* a, const u32* b) {
    asm volatile("mma.sync.aligned.m16n8k16.row.col.f32.bf16.bf16.f32 "
                 "{%0,%1,%2,%3}, {%4,%5,%6,%7}, {%8,%9}, {%0,%1,%2,%3};"
                 : "+f"(d[0]), "+f"(d[1]), "+f"(d[2]), "+f"(d[3])
                 : "r"(a[0]), "r"(a[1]), "r"(a[2]), "r"(a[3]), "r"(b[0]), "r"(b[1]));
}
// per-row 16B-chunk XOR swizzle on 256B-pitch rows
__device__ __host__ __forceinline__ u32 swz(u32 o, u32 row) {
    return o ^ ((row & 7u) << 4);
}

// ---------------- scratch (device globals: no allocation allowed) ----------
__device__ float g_xl[(size_t)N_NODES * HC];     // 25.6 MB
__device__ float g_xr[(size_t)N_NODES * HC];     // 25.6 MB
__device__ int   g_cnt[N_NODES];
__device__ int   g_off[N_NODES + 1];
__device__ int   g_woff[N_NODES];
__device__ int   g_srcs[N_EDGES];
__device__ int   g_blocksum[SCAN_NBLK];
// pre-swizzled B: [hilo][n=256 rows][k=128 bf16] = 2 x 64KB
__device__ unsigned char g_Bsw[2][65536];

// SMEM layout for mma GEMM (dynamic): A hi/lo 2x32KB, B hi/lo 2x64KB
#define SM_A     0
#define SM_B     65536
#define SM_TOTAL 196608

// ---------------- prep: transpose + split W into swizzled bf16 [n][k] ------
__global__ __launch_bounds__(256) void prepB_kernel(const float* __restrict__ Wl,
                                                    const float* __restrict__ Wr) {
    int i = blockIdx.x * 256 + threadIdx.x;
    if (i >= 256 * 64) return;
    int n  = i >> 6;          // output row (col of W): 0..255
    int kp = i & 63;          // k-pair
    int k  = kp * 2;
    const float* W = (n >= HC) ? Wr : Wl;
    int c = n & 127;
    float v0 = W[(size_t)k * HC + c];
    float v1 = W[(size_t)(k + 1) * HC + c];

    __nv_bfloat16 h0 = __float2bfloat16_rn(v0);
    __nv_bfloat16 h1 = __float2bfloat16_rn(v1);
    __nv_bfloat16 e0 = __float2bfloat16_rn(v0 - __bfloat162float(h0));
    __nv_bfloat16 e1 = __float2bfloat16_rn(v1 - __bfloat162float(h1));

    u32 so = swz((u32)(n * 256 + k * 2), (u32)n);
    *(u32*)&g_Bsw[0][so] = (u32)__bfloat16_as_ushort(h0) | ((u32)__bfloat16_as_ushort(h1) << 16);
    *(u32*)&g_Bsw[1][so] = (u32)__bfloat16_as_ushort(e0) | ((u32)__bfloat16_as_ushort(e1) << 16);
}

// ---------------- tensor-core GEMM: [xl|xr] = x @ [Wl|Wr] + dst histogram ---
// 256 threads = 8 warps; warp (wm, wn) owns 64x64 of the 128x256 tile.
// 3 bf16 passes: (Ah,Bh), (Ah,Bl), (Al,Bh) accumulated in fp32 regs.
__global__ __launch_bounds__(256) void gemm_tc(const float* __restrict__ x,
                                               const int* __restrict__ dst) {
    extern __shared__ unsigned char smem[];
    const u32 sbase = smem_u32(smem);
    const int t = threadIdx.x;
    const int w = t >> 5;
    const int l = t & 31;
    const int m0 = blockIdx.x * M_TILE;

    // fused dst histogram (independent; overlaps with loads)
    for (int e = blockIdx.x * 256 + t; e < N_EDGES; e += gridDim.x * 256)
        atomicAdd(&g_cnt[dst[e]], 1);

    // copy pre-swizzled B (128 KB, linear)
    {
        const float4* s = (const float4*)&g_Bsw[0][0];
        float4* d4 = (float4*)(smem + SM_B);
        for (int i = t; i < 131072 / 16; i += 256) d4[i] = s[i];
    }

    // load x tile, split hi/lo bf16, store swizzled ([row][k], 256B pitch)
    for (int i = t; i < 128 * 32; i += 256) {
        int row = i >> 5;
        int k4  = i & 31;           // 4 k-values
        int node = m0 + row;
        float4 v = make_float4(0.f, 0.f, 0.f, 0.f);
        if (node < N_NODES) v = ((const float4*)x)[(size_t)node * (DIM_IN / 4) + k4];

        __nv_bfloat16 h0 = __float2bfloat16_rn(v.x);
        __nv_bfloat16 h1 = __float2bfloat16_rn(v.y);
        __nv_bfloat16 h2 = __float2bfloat16_rn(v.z);
        __nv_bfloat16 h3 = __float2bfloat16_rn(v.w);
        __nv_bfloat16 e0 = __float2bfloat16_rn(v.x - __bfloat162float(h0));
        __nv_bfloat16 e1 = __float2bfloat16_rn(v.y - __bfloat162float(h1));
        __nv_bfloat16 e2 = __float2bfloat16_rn(v.z - __bfloat162float(h2));
        __nv_bfloat16 e3 = __float2bfloat16_rn(v.w - __bfloat162float(h3));

        u64 hi = (u64)((u32)__bfloat16_as_ushort(h0) | ((u32)__bfloat16_as_ushort(h1) << 16))
               | ((u64)((u32)__bfloat16_as_ushort(h2) | ((u32)__bfloat16_as_ushort(h3) << 16)) << 32);
        u64 lo = (u64)((u32)__bfloat16_as_ushort(e0) | ((u32)__bfloat16_as_ushort(e1) << 16))
               | ((u64)((u32)__bfloat16_as_ushort(e2) | ((u32)__bfloat16_as_ushort(e3) << 16)) << 32);

        u32 so = swz((u32)(row * 256 + k4 * 8), (u32)row);
        *(u64*)(smem + SM_A + so)          = hi;
        *(u64*)(smem + SM_A + 32768 + so)  = lo;
    }
    __syncthreads();

    const int wm = w >> 2;      // 0..1
    const int wn = w & 3;       // 0..3
    const int idx8 = l & 7;
    const int g = l >> 3;       // 0..3

    float acc[4][8][4];
#pragma unroll
    for (int mf = 0; mf < 4; mf++)
#pragma unroll
        for (int nf = 0; nf < 8; nf++)
#pragma unroll
            for (int q = 0; q < 4; q++) acc[mf][nf][q] = 0.f;

#pragma unroll 1
    for (int pass = 0; pass < 3; pass++) {
        const u32 abase = sbase + SM_A + ((pass == 2) ? 32768u : 0u);
        const u32 bbase = sbase + SM_B + ((pass == 1) ? 65536u : 0u);
#pragma unroll 1
        for (int ks = 0; ks < 8; ks++) {
            u32 a[4][4];
#pragma unroll
            for (int mf = 0; mf < 4; mf++) {
                u32 row = (u32)(wm * 64 + mf * 16 + (g & 1) * 8 + idx8);
                u32 o = row * 256 + (u32)ks * 32 + (u32)(g >> 1) * 16;
                ldsm_x4(a[mf][0], a[mf][1], a[mf][2], a[mf][3], abase + swz(o, row));
            }
            u32 b[8][2];
#pragma unroll
            for (int nf2 = 0; nf2 < 4; nf2++) {
                u32 row = (u32)(wn * 64 + nf2 * 16 + (g >> 1) * 8 + idx8);
                u32 o = row * 256 + (u32)ks * 32 + (u32)(g & 1) * 16;
                u32 r0, r1, r2, r3;
                ldsm_x4(r0, r1, r2, r3, bbase + swz(o, row));
                b[2 * nf2][0] = r0;     b[2 * nf2][1] = r1;
                b[2 * nf2 + 1][0] = r2; b[2 * nf2 + 1][1] = r3;
            }
#pragma unroll
            for (int mf = 0; mf < 4; mf++)
#pragma unroll
                for (int nf = 0; nf < 8; nf++)
                    mma_bf16(acc[mf][nf], a[mf], b[nf]);
        }
    }

    // epilogue: warps wn<2 -> g_xl, wn>=2 -> g_xr; cols (wn&1)*64 .. +63
    float* outp = (wn < 2) ? g_xl : g_xr;
    const int cbase = (wn & 1) * 64;
#pragma unroll
    for (int mf = 0; mf < 4; mf++) {
#pragma unroll
        for (int nf = 0; nf < 8; nf++) {
            int r0 = m0 + wm * 64 + mf * 16 + (l >> 2);
            int c  = cbase + nf * 8 + (l & 3) * 2;
            if (r0 < N_NODES)
                *(float2*)(outp + (size_t)r0 * HC + c) = make_float2(acc[mf][nf][0], acc[mf][nf][1]);
            int r1 = r0 + 8;
            if (r1 < N_NODES)
                *(float2*)(outp + (size_t)r1 * HC + c) = make_float2(acc[mf][nf][2], acc[mf][nf][3]);
        }
    }
}

// ---------------- CSR build -------------------------------------------------
__global__ void zero_cnt_kernel() {
    int i = blockIdx.x * blockDim.x + threadIdx.x;
    if (i < N_NODES) g_cnt[i] = 0;
}

__global__ __launch_bounds__(256) void scanA_kernel() {
    __shared__ int wsum[8];
    const int t = threadIdx.x;
    const int i0 = blockIdx.x * SCAN_CHUNK + t * 4;

    int4 v = make_int4(0, 0, 0, 0);
    if (i0 < N_NODES) v = *(const int4*)(g_cnt + i0);

    int e1 = v.x;
    int e2 = e1 + v.y;
    int e3 = e2 + v.z;
    int s  = e3 + v.w;

    int incl = s;
#pragma unroll
    for (int d = 1; d < 32; d <<= 1) {
        int u = __shfl_up_sync(0xffffffffu, incl, d);
        if ((t & 31) >= d) incl += u;
    }
    if ((t & 31) == 31) wsum[t >> 5] = incl;
    __syncthreads();

    if (t < 8) {
        int ws = wsum[t];
        int wincl = ws;
#pragma unroll
        for (int d = 1; d < 8; d <<= 1) {
            int u = __shfl_up_sync(0x000000ffu, wincl, d);
            if (t >= d) wincl += u;
        }
        wsum[t] = wincl - ws;
        if (t == 7) g_blocksum[blockIdx.x] = wincl;
    }
    __syncthreads();
    int wbase = wsum[t >> 5];

    const int base = wbase + (incl - s);
    if (i0 < N_NODES)
        *(int4*)(g_off + i0) = make_int4(base, base + e1, base + e2, base + e3);
}

__global__ __launch_bounds__(256) void scanC_kernel() {
    __shared__ int bs[SCAN_NBLK];
    const int t = threadIdx.x;
    if (t < SCAN_NBLK) bs[t] = g_blocksum[t];
    __syncthreads();

    int base = 0;
#pragma unroll 8
    for (int j = 0; j < SCAN_NBLK; j++)
        if (j < blockIdx.x) base += bs[j];

    const int i0 = blockIdx.x * SCAN_CHUNK + t * 4;
    if (i0 < N_NODES) {
        int4 v = *(const int4*)(g_off + i0);
        v.x += base; v.y += base; v.z += base; v.w += base;
        *(int4*)(g_off + i0)  = v;
        *(int4*)(g_woff + i0) = v;
    }
    if (blockIdx.x == 0 && t == 0) g_off[N_NODES] = N_EDGES;
}

__global__ void scatter_kernel(const int* __restrict__ src, const int* __restrict__ dst) {
    int e = blockIdx.x * blockDim.x + threadIdx.x;
    if (e < N_EDGES) {
        int d = dst[e];
        int p = atomicAdd(&g_woff[d], 1);
        g_srcs[p] = src[e];
    }
}

// ---------------- per-node fused attention + aggregation + projection ------
__device__ __forceinline__ float lrelu(float v) {
    return v > 0.f ? v : NEG_SLOPE * v;
}

__global__ __launch_bounds__(256) void node_kernel(const float* __restrict__ att,
                                                   const float* __restrict__ bias,
                                                   const float* __restrict__ Wp,
                                                   const float* __restrict__ bp,
                                                   float* __restrict__ out) {
    __shared__ float Wpt[DIM_OUT][130];
    __shared__ float sbuf[8][HC];

    const int t = threadIdx.x;
    const int w = t >> 5;
    const int l = t & 31;

    for (int i = t; i < HC * DIM_OUT / 4; i += 256) {
        float4 v = ((const float4*)Wp)[i];
        int k = i >> 3;
        int o = (i & 7) * 4;
        Wpt[o + 0][k] = v.x;
        Wpt[o + 1][k] = v.y;
        Wpt[o + 2][k] = v.z;
        Wpt[o + 3][k] = v.w;
    }
    __syncthreads();

    const float4 a4  = *(const float4*)(att + l * 4);
    const float4 b4  = *(const float4*)(bias + l * 4);
    const float  bpl = bp[l];
    const int wg = blockIdx.x * 8 + w;

    for (int nn = 0; nn < 4; nn++) {
        const int node = wg * 4 + nn;
        if (node >= N_NODES) break;

        const float4 xr4 = *(const float4*)(g_xr + (size_t)node * HC + l * 4);
        const int e0 = g_off[node];
        const int e1 = g_off[node + 1];

        float denom = 0.f;
        float4 acc = make_float4(0.f, 0.f, 0.f, 0.f);

        for (int base = e0; base < e1; base += 32) {
            const int nE = min(32, e1 - base);
            int sv = 0;
            if (l < nE) sv = g_srcs[base + l];

            for (int j = 0; j < nE; j += 2) {
                const int s0 = __shfl_sync(0xffffffffu, sv, j);
                const int s1 = __shfl_sync(0xffffffffu, sv, (j + 1) & 31);
                const bool h1 = (j + 1) < nE;

                const float4 x0 = *(const float4*)(g_xl + (size_t)s0 * HC + l * 4);
                float4 x1 = make_float4(0.f, 0.f, 0.f, 0.f);
                if (h1) x1 = *(const float4*)(g_xl + (size_t)s1 * HC + l * 4);

                float p0 = a4.x * lrelu(x0.x + xr4.x)
                         + a4.y * lrelu(x0.y + xr4.y)
                         + a4.z * lrelu(x0.z + xr4.z)
                         + a4.w * lrelu(x0.w + xr4.w);
                float p1 = a4.x * lrelu(x1.x + xr4.x)
                         + a4.y * lrelu(x1.y + xr4.y)
                         + a4.z * lrelu(x1.z + xr4.z)
                         + a4.w * lrelu(x1.w + xr4.w);

                p0 += __shfl_xor_sync(0xffffffffu, p0, 4);
                p1 += __shfl_xor_sync(0xffffffffu, p1, 4);
                p0 += __shfl_xor_sync(0xffffffffu, p0, 2);
                p1 += __shfl_xor_sync(0xffffffffu, p1, 2);
                p0 += __shfl_xor_sync(0xffffffffu, p0, 1);
                p1 += __shfl_xor_sync(0xffffffffu, p1, 1);

                const float ev0 = __expf(p0);
                const float ev1 = h1 ? __expf(p1) : 0.f;
                denom += ev0 + ev1;
                acc.x += x0.x * ev0 + x1.x * ev1;
                acc.y += x0.y * ev0 + x1.y * ev1;
                acc.z += x0.z * ev0 + x1.z * ev1;
                acc.w += x0.w * ev0 + x1.w * ev1;
            }
        }

        const float inv = 1.f / (denom + 1e-16f);
        sbuf[w][4 * l + 0] = acc.x * inv + b4.x;
        sbuf[w][4 * l + 1] = acc.y * inv + b4.y;
        sbuf[w][4 * l + 2] = acc.z * inv + b4.z;
        sbuf[w][4 * l + 3] = acc.w * inv + b4.w;
        __syncwarp();

        const u64* sp = (const u64*)&sbuf[w][0];
        const u64* wp = (const u64*)&Wpt[l][0];
        u64 r2 = pack2(bpl, 0.f);
#pragma unroll 8
        for (int k2 = 0; k2 < HC / 2; k2++) ffma2(r2, sp[k2], wp[k2]);
        float2 rr = unpack2(r2);
        out[(size_t)node * DIM_OUT + l] = rr.x + rr.y;
        __syncwarp();
    }
}

// ---------------- launch ----------------------------------------------------
extern "C" void kernel_launch(void* const* d_in, const int* in_sizes, int n_in,
                              void* d_out, int out_size) {
    const float* x    = (const float*)d_in[0];
    const int*   ei   = (const int*)d_in[1];
    const float* Wl   = (const float*)d_in[2];
    const float* Wr   = (const float*)d_in[3];
    const float* att  = (const float*)d_in[4];
    const float* bias = (const float*)d_in[5];
    const float* Wp   = (const float*)d_in[6];
    const float* bp   = (const float*)d_in[7];
    const int* src = ei;
    const int* dst = ei + N_EDGES;

    // idempotent, deterministic config (needed for 192KB dynamic smem)
    cudaFuncSetAttribute(gemm_tc, cudaFuncAttributeMaxDynamicSharedMemorySize, SM_TOTAL);

    zero_cnt_kernel<<<(N_NODES + 255) / 256, 256>>>();
    prepB_kernel<<<64, 256>>>(Wl, Wr);
    gemm_tc<<<N_MTILES, 256, SM_TOTAL>>>(x, dst);   // + hidden histogram
    scanA_kernel<<<SCAN_NBLK, 256>>>();
    scanC_kernel<<<SCAN_NBLK, 256>>>();
    scatter_kernel<<<(N_EDGES + 255) / 256, 256>>>(src, dst);
    node_kernel<<<(N_NODES + 31) / 32, 256>>>(att, bias, Wp, bp, (float*)d_out);
}

// round 6
// speedup vs baseline: 1.7265x; 1.0781x over previous
#include <cuda_runtime.h>
#include <cuda_bf16.h>
#include <math.h>

#define N_NODES 50000
#define N_EDGES 640000
#define DIM_IN  128
#define HC      128
#define DIM_OUT 32
#define HEADS   4
#define NEG_SLOPE 0.2f

#define SCAN_CHUNK 1024
#define SCAN_NBLK  ((N_NODES + SCAN_CHUNK - 1) / SCAN_CHUNK)   // 49

#define M_TILE   128
#define N_MTILES ((N_NODES + M_TILE - 1) / M_TILE)             // 391

typedef unsigned long long u64;
typedef unsigned int u32;

// ---------------- f32x2 helpers (node-kernel projection) --------------------
__device__ __forceinline__ u64 pack2(float lo, float hi) {
    u64 r; asm("mov.b64 %0, {%1, %2};" : "=l"(r) : "f"(lo), "f"(hi)); return r;
}
__device__ __forceinline__ void ffma2(u64& d, u64 a, u64 b) {
    asm("fma.rn.f32x2 %0, %1, %2, %3;" : "=l"(d) : "l"(a), "l"(b), "l"(d));
}
__device__ __forceinline__ float2 unpack2(u64 v) {
    float2 f; asm("mov.b64 {%0, %1}, %2;" : "=f"(f.x), "=f"(f.y) : "l"(v)); return f;
}

// ---------------- warp-MMA helpers (compute_103-safe: sm_80-era ops) --------
__device__ __forceinline__ u32 smem_u32(const void* p) {
    u32 a;
    asm("{ .reg .u64 tmp; cvta.to.shared.u64 tmp, %1; cvt.u32.u64 %0, tmp; }"
        : "=r"(a) : "l"(p));
    return a;
}
__device__ __forceinline__ void ldsm_x4(u32& r0, u32& r1, u32& r2, u32& r3, u32 addr) {
    asm volatile("ldmatrix.sync.aligned.m8n8.x4.shared.b16 {%0,%1,%2,%3}, [%4];"
                 : "=r"(r0), "=r"(r1), "=r"(r2), "=r"(r3) : "r"(addr));
}
__device__ __forceinline__ void mma_bf16(float* d, const u32* a, const u32* b) {
    asm volatile("mma.sync.aligned.m16n8k16.row.col.f32.bf16.bf16.f32 "
                 "{%0,%1,%2,%3}, {%4,%5,%6,%7}, {%8,%9}, {%0,%1,%2,%3};"
                 : "+f"(d[0]), "+f"(d[1]), "+f"(d[2]), "+f"(d[3])
                 : "r"(a[0]), "r"(a[1]), "r"(a[2]), "r"(a[3]), "r"(b[0]), "r"(b[1]));
}
// per-row 16B-chunk XOR swizzle on 256B-pitch rows
__device__ __host__ __forceinline__ u32 swz(u32 o, u32 row) {
    return o ^ ((row & 7u) << 4);
}

// ---------------- scratch (device globals: no allocation allowed) ----------
__device__ float g_xl[(size_t)N_NODES * HC];     // 25.6 MB
__device__ float g_xr[(size_t)N_NODES * HC];     // 25.6 MB
__device__ int   g_cnt[N_NODES];
__device__ int   g_off[N_NODES + 1];
__device__ int   g_woff[N_NODES];
__device__ int   g_srcs[N_EDGES];
__device__ int   g_blocksum[SCAN_NBLK];
// pre-swizzled B: [hilo][n=256 rows][k=128 bf16] = 2 x 64KB
__device__ unsigned char g_Bsw[2][65536];

// SMEM layout for mma GEMM (dynamic): A hi/lo 2x32KB, B hi/lo 2x64KB
#define SM_A     0
#define SM_B     65536
#define SM_TOTAL 196608

// ---------------- prep: transpose + split W into swizzled bf16 [n][k] ------
__global__ __launch_bounds__(256) void prepB_kernel(const float* __restrict__ Wl,
                                                    const float* __restrict__ Wr) {
    int i = blockIdx.x * 256 + threadIdx.x;
    if (i >= 256 * 64) return;
    int n  = i >> 6;          // output row (col of W): 0..255
    int kp = i & 63;          // k-pair
    int k  = kp * 2;
    const float* W = (n >= HC) ? Wr : Wl;
    int c = n & 127;
    float v0 = W[(size_t)k * HC + c];
    float v1 = W[(size_t)(k + 1) * HC + c];

    __nv_bfloat16 h0 = __float2bfloat16_rn(v0);
    __nv_bfloat16 h1 = __float2bfloat16_rn(v1);
    __nv_bfloat16 e0 = __float2bfloat16_rn(v0 - __bfloat162float(h0));
    __nv_bfloat16 e1 = __float2bfloat16_rn(v1 - __bfloat162float(h1));

    u32 so = swz((u32)(n * 256 + k * 2), (u32)n);
    *(u32*)&g_Bsw[0][so] = (u32)__bfloat16_as_ushort(h0) | ((u32)__bfloat16_as_ushort(h1) << 16);
    *(u32*)&g_Bsw[1][so] = (u32)__bfloat16_as_ushort(e0) | ((u32)__bfloat16_as_ushort(e1) << 16);
}

// ---------------- tensor-core GEMM: [xl|xr] = x @ [Wl|Wr] -------------------
// 256 threads = 8 warps; warp (wm, wn) owns 64x64 of the 128x256 tile.
// 3 bf16 passes: (Ah,Bh), (Ah,Bl), (Al,Bh) accumulated in fp32 regs.
__global__ __launch_bounds__(256) void gemm_tc(const float* __restrict__ x) {
    extern __shared__ unsigned char smem[];
    const u32 sbase = smem_u32(smem);
    const int t = threadIdx.x;
    const int w = t >> 5;
    const int l = t & 31;
    const int m0 = blockIdx.x * M_TILE;

    // copy pre-swizzled B (128 KB, linear)
    {
        const float4* s = (const float4*)&g_Bsw[0][0];
        float4* d4 = (float4*)(smem + SM_B);
        for (int i = t; i < 131072 / 16; i += 256) d4[i] = s[i];
    }

    // load x tile, split hi/lo bf16, store swizzled ([row][k], 256B pitch)
    for (int i = t; i < 128 * 32; i += 256) {
        int row = i >> 5;
        int k4  = i & 31;           // 4 k-values
        int node = m0 + row;
        float4 v = make_float4(0.f, 0.f, 0.f, 0.f);
        if (node < N_NODES) v = ((const float4*)x)[(size_t)node * (DIM_IN / 4) + k4];

        __nv_bfloat16 h0 = __float2bfloat16_rn(v.x);
        __nv_bfloat16 h1 = __float2bfloat16_rn(v.y);
        __nv_bfloat16 h2 = __float2bfloat16_rn(v.z);
        __nv_bfloat16 h3 = __float2bfloat16_rn(v.w);
        __nv_bfloat16 e0 = __float2bfloat16_rn(v.x - __bfloat162float(h0));
        __nv_bfloat16 e1 = __float2bfloat16_rn(v.y - __bfloat162float(h1));
        __nv_bfloat16 e2 = __float2bfloat16_rn(v.z - __bfloat162float(h2));
        __nv_bfloat16 e3 = __float2bfloat16_rn(v.w - __bfloat162float(h3));

        u64 hi = (u64)((u32)__bfloat16_as_ushort(h0) | ((u32)__bfloat16_as_ushort(h1) << 16))
               | ((u64)((u32)__bfloat16_as_ushort(h2) | ((u32)__bfloat16_as_ushort(h3) << 16)) << 32);
        u64 lo = (u64)((u32)__bfloat16_as_ushort(e0) | ((u32)__bfloat16_as_ushort(e1) << 16))
               | ((u64)((u32)__bfloat16_as_ushort(e2) | ((u32)__bfloat16_as_ushort(e3) << 16)) << 32);

        u32 so = swz((u32)(row * 256 + k4 * 8), (u32)row);
        *(u64*)(smem + SM_A + so)          = hi;
        *(u64*)(smem + SM_A + 32768 + so)  = lo;
    }
    __syncthreads();

    const int wm = w >> 2;      // 0..1
    const int wn = w & 3;       // 0..3
    const int idx8 = l & 7;
    const int g = l >> 3;       // 0..3

    float acc[4][8][4];
#pragma unroll
    for (int mf = 0; mf < 4; mf++)
#pragma unroll
        for (int nf = 0; nf < 8; nf++)
#pragma unroll
            for (int q = 0; q < 4; q++) acc[mf][nf][q] = 0.f;

#pragma unroll 1
    for (int pass = 0; pass < 3; pass++) {
        const u32 abase = sbase + SM_A + ((pass == 2) ? 32768u : 0u);
        const u32 bbase = sbase + SM_B + ((pass == 1) ? 65536u : 0u);
#pragma unroll 1
        for (int ks = 0; ks < 8; ks++) {
            u32 a[4][4];
#pragma unroll
            for (int mf = 0; mf < 4; mf++) {
                u32 row = (u32)(wm * 64 + mf * 16 + (g & 1) * 8 + idx8);
                u32 o = row * 256 + (u32)ks * 32 + (u32)(g >> 1) * 16;
                ldsm_x4(a[mf][0], a[mf][1], a[mf][2], a[mf][3], abase + swz(o, row));
            }
            u32 b[8][2];
#pragma unroll
            for (int nf2 = 0; nf2 < 4; nf2++) {
                u32 row = (u32)(wn * 64 + nf2 * 16 + (g >> 1) * 8 + idx8);
                u32 o = row * 256 + (u32)ks * 32 + (u32)(g & 1) * 16;
                u32 r0, r1, r2, r3;
                ldsm_x4(r0, r1, r2, r3, bbase + swz(o, row));
                b[2 * nf2][0] = r0;     b[2 * nf2][1] = r1;
                b[2 * nf2 + 1][0] = r2; b[2 * nf2 + 1][1] = r3;
            }
#pragma unroll
            for (int mf = 0; mf < 4; mf++)
#pragma unroll
                for (int nf = 0; nf < 8; nf++)
                    mma_bf16(acc[mf][nf], a[mf], b[nf]);
        }
    }

    // epilogue: warps wn<2 -> g_xl, wn>=2 -> g_xr; cols (wn&1)*64 .. +63
    float* outp = (wn < 2) ? g_xl : g_xr;
    const int cbase = (wn & 1) * 64;
#pragma unroll
    for (int mf = 0; mf < 4; mf++) {
#pragma unroll
        for (int nf = 0; nf < 8; nf++) {
            int r0 = m0 + wm * 64 + mf * 16 + (l >> 2);
            int c  = cbase + nf * 8 + (l & 3) * 2;
            if (r0 < N_NODES)
                *(float2*)(outp + (size_t)r0 * HC + c) = make_float2(acc[mf][nf][0], acc[mf][nf][1]);
            int r1 = r0 + 8;
            if (r1 < N_NODES)
                *(float2*)(outp + (size_t)r1 * HC + c) = make_float2(acc[mf][nf][2], acc[mf][nf][3]);
        }
    }
}

// ---------------- CSR build -------------------------------------------------
__global__ void zero_cnt_kernel() {
    int i = blockIdx.x * blockDim.x + threadIdx.x;
    if (i < N_NODES) g_cnt[i] = 0;
}

__global__ void hist_kernel(const int* __restrict__ dst) {
    int e = blockIdx.x * blockDim.x + threadIdx.x;
    if (e < N_EDGES) atomicAdd(&g_cnt[dst[e]], 1);
}

__global__ __launch_bounds__(256) void scanA_kernel() {
    __shared__ int wsum[8];
    const int t = threadIdx.x;
    const int i0 = blockIdx.x * SCAN_CHUNK + t * 4;

    int4 v = make_int4(0, 0, 0, 0);
    if (i0 < N_NODES) v = *(const int4*)(g_cnt + i0);

    int e1 = v.x;
    int e2 = e1 + v.y;
    int e3 = e2 + v.z;
    int s  = e3 + v.w;

    int incl = s;
#pragma unroll
    for (int d = 1; d < 32; d <<= 1) {
        int u = __shfl_up_sync(0xffffffffu, incl, d);
        if ((t & 31) >= d) incl += u;
    }
    if ((t & 31) == 31) wsum[t >> 5] = incl;
    __syncthreads();

    if (t < 8) {
        int ws = wsum[t];
        int wincl = ws;
#pragma unroll
        for (int d = 1; d < 8; d <<= 1) {
            int u = __shfl_up_sync(0x000000ffu, wincl, d);
            if (t >= d) wincl += u;
        }
        wsum[t] = wincl - ws;
        if (t == 7) g_blocksum[blockIdx.x] = wincl;
    }
    __syncthreads();
    int wbase = wsum[t >> 5];

    const int base = wbase + (incl - s);
    if (i0 < N_NODES)
        *(int4*)(g_off + i0) = make_int4(base, base + e1, base + e2, base + e3);
}

__global__ __launch_bounds__(256) void scanC_kernel() {
    __shared__ int bs[SCAN_NBLK];
    const int t = threadIdx.x;
    if (t < SCAN_NBLK) bs[t] = g_blocksum[t];
    __syncthreads();

    int base = 0;
#pragma unroll 8
    for (int j = 0; j < SCAN_NBLK; j++)
        if (j < blockIdx.x) base += bs[j];

    const int i0 = blockIdx.x * SCAN_CHUNK + t * 4;
    if (i0 < N_NODES) {
        int4 v = *(const int4*)(g_off + i0);
        v.x += base; v.y += base; v.z += base; v.w += base;
        *(int4*)(g_off + i0)  = v;
        *(int4*)(g_woff + i0) = v;
    }
    if (blockIdx.x == 0 && t == 0) g_off[N_NODES] = N_EDGES;
}

__global__ void scatter_kernel(const int* __restrict__ src, const int* __restrict__ dst) {
    int e = blockIdx.x * blockDim.x + threadIdx.x;
    if (e < N_EDGES) {
        int d = dst[e];
        int p = atomicAdd(&g_woff[d], 1);
        g_srcs[p] = src[e];
    }
}

// ---------------- per-node fused attention + aggregation + projection ------
__device__ __forceinline__ float lrelu(float v) {
    return v > 0.f ? v : NEG_SLOPE * v;
}

__global__ __launch_bounds__(256) void node_kernel(const float* __restrict__ att,
                                                   const float* __restrict__ bias,
                                                   const float* __restrict__ Wp,
                                                   const float* __restrict__ bp,
                                                   float* __restrict__ out) {
    __shared__ float Wpt[DIM_OUT][130];
    __shared__ float sbuf[8][HC];

    const int t = threadIdx.x;
    const int w = t >> 5;
    const int l = t & 31;

    for (int i = t; i < HC * DIM_OUT / 4; i += 256) {
        float4 v = ((const float4*)Wp)[i];
        int k = i >> 3;
        int o = (i & 7) * 4;
        Wpt[o + 0][k] = v.x;
        Wpt[o + 1][k] = v.y;
        Wpt[o + 2][k] = v.z;
        Wpt[o + 3][k] = v.w;
    }
    __syncthreads();

    const float4 a4  = *(const float4*)(att + l * 4);
    const float4 b4  = *(const float4*)(bias + l * 4);
    const float  bpl = bp[l];
    const int wg = blockIdx.x * 8 + w;

    for (int nn = 0; nn < 4; nn++) {
        const int node = wg * 4 + nn;
        if (node >= N_NODES) break;

        const float4 xr4 = *(const float4*)(g_xr + (size_t)node * HC + l * 4);
        const int e0 = g_off[node];
        const int e1 = g_off[node + 1];

        float denom = 0.f;
        float4 acc = make_float4(0.f, 0.f, 0.f, 0.f);

        for (int base = e0; base < e1; base += 32) {
            const int nE = min(32, e1 - base);
            int sv = 0;
            if (l < nE) sv = g_srcs[base + l];

            for (int j = 0; j < nE; j += 2) {
                const int s0 = __shfl_sync(0xffffffffu, sv, j);
                const int s1 = __shfl_sync(0xffffffffu, sv, (j + 1) & 31);
                const bool h1 = (j + 1) < nE;

                const float4 x0 = *(const float4*)(g_xl + (size_t)s0 * HC + l * 4);
                float4 x1 = make_float4(0.f, 0.f, 0.f, 0.f);
                if (h1) x1 = *(const float4*)(g_xl + (size_t)s1 * HC + l * 4);

                float p0 = a4.x * lrelu(x0.x + xr4.x)
                         + a4.y * lrelu(x0.y + xr4.y)
                         + a4.z * lrelu(x0.z + xr4.z)
                         + a4.w * lrelu(x0.w + xr4.w);
                float p1 = a4.x * lrelu(x1.x + xr4.x)
                         + a4.y * lrelu(x1.y + xr4.y)
                         + a4.z * lrelu(x1.z + xr4.z)
                         + a4.w * lrelu(x1.w + xr4.w);

                p0 += __shfl_xor_sync(0xffffffffu, p0, 4);
                p1 += __shfl_xor_sync(0xffffffffu, p1, 4);
                p0 += __shfl_xor_sync(0xffffffffu, p0, 2);
                p1 += __shfl_xor_sync(0xffffffffu, p1, 2);
                p0 += __shfl_xor_sync(0xffffffffu, p0, 1);
                p1 += __shfl_xor_sync(0xffffffffu, p1, 1);

                const float ev0 = __expf(p0);
                const float ev1 = h1 ? __expf(p1) : 0.f;
                denom += ev0 + ev1;
                acc.x += x0.x * ev0 + x1.x * ev1;
                acc.y += x0.y * ev0 + x1.y * ev1;
                acc.z += x0.z * ev0 + x1.z * ev1;
                acc.w += x0.w * ev0 + x1.w * ev1;
            }
        }

        const float inv = 1.f / (denom + 1e-16f);
        sbuf[w][4 * l + 0] = acc.x * inv + b4.x;
        sbuf[w][4 * l + 1] = acc.y * inv + b4.y;
        sbuf[w][4 * l + 2] = acc.z * inv + b4.z;
        sbuf[w][4 * l + 3] = acc.w * inv + b4.w;
        __syncwarp();

        const u64* sp = (const u64*)&sbuf[w][0];
        const u64* wp = (const u64*)&Wpt[l][0];
        u64 r2 = pack2(bpl, 0.f);
#pragma unroll 8
        for (int k2 = 0; k2 < HC / 2; k2++) ffma2(r2, sp[k2], wp[k2]);
        float2 rr = unpack2(r2);
        out[(size_t)node * DIM_OUT + l] = rr.x + rr.y;
        __syncwarp();
    }
}

// ---------------- launch: two-stream fork/join inside the captured graph ----
extern "C" void kernel_launch(void* const* d_in, const int* in_sizes, int n_in,
                              void* d_out, int out_size) {
    const float* x    = (const float*)d_in[0];
    const int*   ei   = (const int*)d_in[1];
    const float* Wl   = (const float*)d_in[2];
    const float* Wr   = (const float*)d_in[3];
    const float* att  = (const float*)d_in[4];
    const float* bias = (const float*)d_in[5];
    const float* Wp   = (const float*)d_in[6];
    const float* bp   = (const float*)d_in[7];
    const int* src = ei;
    const int* dst = ei + N_EDGES;

    cudaFuncSetAttribute(gemm_tc, cudaFuncAttributeMaxDynamicSharedMemorySize, SM_TOTAL);

    // lazily created, reused every call (no device memory involved)
    static cudaStream_t s1 = nullptr;
    static cudaEvent_t evFork = nullptr, evJoin = nullptr;
    if (s1 == nullptr) {
        cudaStreamCreateWithFlags(&s1, cudaStreamNonBlocking);
        cudaEventCreateWithFlags(&evFork, cudaEventDisableTiming);
        cudaEventCreateWithFlags(&evJoin, cudaEventDisableTiming);
    }

    // fork: CSR-build branch on s1
    cudaEventRecord(evFork, 0);
    cudaStreamWaitEvent(s1, evFork, 0);
    zero_cnt_kernel<<<(N_NODES + 255) / 256, 256, 0, s1>>>();
    hist_kernel<<<(N_EDGES + 255) / 256, 256, 0, s1>>>(dst);
    scanA_kernel<<<SCAN_NBLK, 256, 0, s1>>>();
    scanC_kernel<<<SCAN_NBLK, 256, 0, s1>>>();
    scatter_kernel<<<(N_EDGES + 255) / 256, 256, 0, s1>>>(src, dst);
    cudaEventRecord(evJoin, s1);

    // main branch: GEMM
    prepB_kernel<<<64, 256>>>(Wl, Wr);
    gemm_tc<<<N_MTILES, 256, SM_TOTAL>>>(x);

    // join, then the fused node phase
    cudaStreamWaitEvent(0, evJoin, 0);
    node_kernel<<<(N_NODES + 31) / 32, 256>>>(att, bias, Wp, bp, (float*)d_out);
}

// round 7
// speedup vs baseline: 1.8554x; 1.0746x over previous
#include <cuda_runtime.h>
#include <cuda_bf16.h>
#include <cuda_fp16.h>
#include <math.h>

#define N_NODES 50000
#define N_EDGES 640000
#define DIM_IN  128
#define HC      128
#define DIM_OUT 32
#define HEADS   4
#define NEG_SLOPE 0.2f

#define SCAN_CHUNK 1024
#define SCAN_NBLK  ((N_NODES + SCAN_CHUNK - 1) / SCAN_CHUNK)   // 49

#define M_TILE   128
#define N_MTILES ((N_NODES + M_TILE - 1) / M_TILE)             // 391

typedef unsigned long long u64;
typedef unsigned int u32;

// ---------------- f32x2 helpers (node-kernel projection) --------------------
__device__ __forceinline__ u64 pack2(float lo, float hi) {
    u64 r; asm("mov.b64 %0, {%1, %2};" : "=l"(r) : "f"(lo), "f"(hi)); return r;
}
__device__ __forceinline__ void ffma2(u64& d, u64 a, u64 b) {
    asm("fma.rn.f32x2 %0, %1, %2, %3;" : "=l"(d) : "l"(a), "l"(b), "l"(d));
}
__device__ __forceinline__ float2 unpack2(u64 v) {
    float2 f; asm("mov.b64 {%0, %1}, %2;" : "=f"(f.x), "=f"(f.y) : "l"(v)); return f;
}

// ---------------- warp-MMA helpers (compute_103-safe: sm_80-era ops) --------
__device__ __forceinline__ u32 smem_u32(const void* p) {
    u32 a;
    asm("{ .reg .u64 tmp; cvta.to.shared.u64 tmp, %1; cvt.u32.u64 %0, tmp; }"
        : "=r"(a) : "l"(p));
    return a;
}
__device__ __forceinline__ void ldsm_x4(u32& r0, u32& r1, u32& r2, u32& r3, u32 addr) {
    asm volatile("ldmatrix.sync.aligned.m8n8.x4.shared.b16 {%0,%1,%2,%3}, [%4];"
                 : "=r"(r0), "=r"(r1), "=r"(r2), "=r"(r3) : "r"(addr));
}
__device__ __forceinline__ void mma_bf16(float* d, const u32* a, const u32* b) {
    asm volatile("mma.sync.aligned.m16n8k16.row.col.f32.bf16.bf16.f32 "
                 "{%0,%1,%2,%3}, {%4,%5,%6,%7}, {%8,%9}, {%0,%1,%2,%3};"
                 : "+f"(d[0]), "+f"(d[1]), "+f"(d[2]), "+f"(d[3])
                 : "r"(a[0]), "r"(a[1]), "r"(a[2]), "r"(a[3]), "r"(b[0]), "r"(b[1]));
}
// per-row 16B-chunk XOR swizzle on 256B-pitch rows
__device__ __host__ __forceinline__ u32 swz(u32 o, u32 row) {
    return o ^ ((row & 7u) << 4);
}

// ---------------- scratch (device globals: no allocation allowed) ----------
__device__ __half g_xl[(size_t)N_NODES * HC];    // 12.8 MB (fp16: gather payload)
__device__ float  g_xr[(size_t)N_NODES * HC];    // 25.6 MB
__device__ int   g_cnt[N_NODES];
__device__ int   g_off[N_NODES + 1];
__device__ int   g_woff[N_NODES];
__device__ int   g_srcs[N_EDGES];
__device__ int   g_blocksum[SCAN_NBLK];
// pre-swizzled B: [hilo][n=256 rows][k=128 bf16] = 2 x 64KB
__device__ unsigned char g_Bsw[2][65536];

// SMEM layout for mma GEMM (dynamic): A hi/lo 2x32KB, B hi/lo 2x64KB
#define SM_A     0
#define SM_B     65536
#define SM_TOTAL 196608

// ---------------- prep: transpose + split W into swizzled bf16 [n][k] ------
__global__ __launch_bounds__(256) void prepB_kernel(const float* __restrict__ Wl,
                                                    const float* __restrict__ Wr) {
    int i = blockIdx.x * 256 + threadIdx.x;
    if (i >= 256 * 64) return;
    int n  = i >> 6;          // output row (col of W): 0..255
    int kp = i & 63;          // k-pair
    int k  = kp * 2;
    const float* W = (n >= HC) ? Wr : Wl;
    int c = n & 127;
    float v0 = W[(size_t)k * HC + c];
    float v1 = W[(size_t)(k + 1) * HC + c];

    __nv_bfloat16 h0 = __float2bfloat16_rn(v0);
    __nv_bfloat16 h1 = __float2bfloat16_rn(v1);
    __nv_bfloat16 e0 = __float2bfloat16_rn(v0 - __bfloat162float(h0));
    __nv_bfloat16 e1 = __float2bfloat16_rn(v1 - __bfloat162float(h1));

    u32 so = swz((u32)(n * 256 + k * 2), (u32)n);
    *(u32*)&g_Bsw[0][so] = (u32)__bfloat16_as_ushort(h0) | ((u32)__bfloat16_as_ushort(h1) << 16);
    *(u32*)&g_Bsw[1][so] = (u32)__bfloat16_as_ushort(e0) | ((u32)__bfloat16_as_ushort(e1) << 16);
}

// ---------------- tensor-core GEMM: [xl|xr] = x @ [Wl|Wr] -------------------
// 256 threads = 8 warps; warp (wm, wn) owns 64x64 of the 128x256 tile.
// 3 bf16 passes: (Ah,Bh), (Ah,Bl), (Al,Bh) accumulated in fp32 regs.
__global__ __launch_bounds__(256) void gemm_tc(const float* __restrict__ x) {
    extern __shared__ unsigned char smem[];
    const u32 sbase = smem_u32(smem);
    const int t = threadIdx.x;
    const int w = t >> 5;
    const int l = t & 31;
    const int m0 = blockIdx.x * M_TILE;

    // copy pre-swizzled B (128 KB, linear)
    {
        const float4* s = (const float4*)&g_Bsw[0][0];
        float4* d4 = (float4*)(smem + SM_B);
        for (int i = t; i < 131072 / 16; i += 256) d4[i] = s[i];
    }

    // load x tile, split hi/lo bf16, store swizzled ([row][k], 256B pitch)
    for (int i = t; i < 128 * 32; i += 256) {
        int row = i >> 5;
        int k4  = i & 31;           // 4 k-values
        int node = m0 + row;
        float4 v = make_float4(0.f, 0.f, 0.f, 0.f);
        if (node < N_NODES) v = ((const float4*)x)[(size_t)node * (DIM_IN / 4) + k4];

        __nv_bfloat16 h0 = __float2bfloat16_rn(v.x);
        __nv_bfloat16 h1 = __float2bfloat16_rn(v.y);
        __nv_bfloat16 h2 = __float2bfloat16_rn(v.z);
        __nv_bfloat16 h3 = __float2bfloat16_rn(v.w);
        __nv_bfloat16 e0 = __float2bfloat16_rn(v.x - __bfloat162float(h0));
        __nv_bfloat16 e1 = __float2bfloat16_rn(v.y - __bfloat162float(h1));
        __nv_bfloat16 e2 = __float2bfloat16_rn(v.z - __bfloat162float(h2));
        __nv_bfloat16 e3 = __float2bfloat16_rn(v.w - __bfloat162float(h3));

        u64 hi = (u64)((u32)__bfloat16_as_ushort(h0) | ((u32)__bfloat16_as_ushort(h1) << 16))
               | ((u64)((u32)__bfloat16_as_ushort(h2) | ((u32)__bfloat16_as_ushort(h3) << 16)) << 32);
        u64 lo = (u64)((u32)__bfloat16_as_ushort(e0) | ((u32)__bfloat16_as_ushort(e1) << 16))
               | ((u64)((u32)__bfloat16_as_ushort(e2) | ((u32)__bfloat16_as_ushort(e3) << 16)) << 32);

        u32 so = swz((u32)(row * 256 + k4 * 8), (u32)row);
        *(u64*)(smem + SM_A + so)          = hi;
        *(u64*)(smem + SM_A + 32768 + so)  = lo;
    }
    __syncthreads();

    const int wm = w >> 2;      // 0..1
    const int wn = w & 3;       // 0..3
    const int idx8 = l & 7;
    const int g = l >> 3;       // 0..3

    float acc[4][8][4];
#pragma unroll
    for (int mf = 0; mf < 4; mf++)
#pragma unroll
        for (int nf = 0; nf < 8; nf++)
#pragma unroll
            for (int q = 0; q < 4; q++) acc[mf][nf][q] = 0.f;

#pragma unroll 1
    for (int pass = 0; pass < 3; pass++) {
        const u32 abase = sbase + SM_A + ((pass == 2) ? 32768u : 0u);
        const u32 bbase = sbase + SM_B + ((pass == 1) ? 65536u : 0u);
#pragma unroll 1
        for (int ks = 0; ks < 8; ks++) {
            u32 a[4][4];
#pragma unroll
            for (int mf = 0; mf < 4; mf++) {
                u32 row = (u32)(wm * 64 + mf * 16 + (g & 1) * 8 + idx8);
                u32 o = row * 256 + (u32)ks * 32 + (u32)(g >> 1) * 16;
                ldsm_x4(a[mf][0], a[mf][1], a[mf][2], a[mf][3], abase + swz(o, row));
            }
            u32 b[8][2];
#pragma unroll
            for (int nf2 = 0; nf2 < 4; nf2++) {
                u32 row = (u32)(wn * 64 + nf2 * 16 + (g >> 1) * 8 + idx8);
                u32 o = row * 256 + (u32)ks * 32 + (u32)(g & 1) * 16;
                u32 r0, r1, r2, r3;
                ldsm_x4(r0, r1, r2, r3, bbase + swz(o, row));
                b[2 * nf2][0] = r0;     b[2 * nf2][1] = r1;
                b[2 * nf2 + 1][0] = r2; b[2 * nf2 + 1][1] = r3;
            }
#pragma unroll
            for (int mf = 0; mf < 4; mf++)
#pragma unroll
                for (int nf = 0; nf < 8; nf++)
                    mma_bf16(acc[mf][nf], a[mf], b[nf]);
        }
    }

    // epilogue: warps wn<2 -> g_xl (fp16), wn>=2 -> g_xr (fp32)
    const int cbase = (wn & 1) * 64;
#pragma unroll
    for (int mf = 0; mf < 4; mf++) {
#pragma unroll
        for (int nf = 0; nf < 8; nf++) {
            int r0 = m0 + wm * 64 + mf * 16 + (l >> 2);
            int r1 = r0 + 8;
            int c  = cbase + nf * 8 + (l & 3) * 2;
            if (wn < 2) {
                if (r0 < N_NODES)
                    *(__half2*)(g_xl + (size_t)r0 * HC + c) =
                        __floats2half2_rn(acc[mf][nf][0], acc[mf][nf][1]);
                if (r1 < N_NODES)
                    *(__half2*)(g_xl + (size_t)r1 * HC + c) =
                        __floats2half2_rn(acc[mf][nf][2], acc[mf][nf][3]);
            } else {
                if (r0 < N_NODES)
                    *(float2*)(g_xr + (size_t)r0 * HC + c) = make_float2(acc[mf][nf][0], acc[mf][nf][1]);
                if (r1 < N_NODES)
                    *(float2*)(g_xr + (size_t)r1 * HC + c) = make_float2(acc[mf][nf][2], acc[mf][nf][3]);
            }
        }
    }
}

// ---------------- CSR build -------------------------------------------------
__global__ void zero_cnt_kernel() {
    int i = blockIdx.x * blockDim.x + threadIdx.x;
    if (i < N_NODES) g_cnt[i] = 0;
}

__global__ void hist_kernel(const int* __restrict__ dst) {
    int e = blockIdx.x * blockDim.x + threadIdx.x;
    if (e < N_EDGES) atomicAdd(&g_cnt[dst[e]], 1);
}

__global__ __launch_bounds__(256) void scanA_kernel() {
    __shared__ int wsum[8];
    const int t = threadIdx.x;
    const int i0 = blockIdx.x * SCAN_CHUNK + t * 4;

    int4 v = make_int4(0, 0, 0, 0);
    if (i0 < N_NODES) v = *(const int4*)(g_cnt + i0);

    int e1 = v.x;
    int e2 = e1 + v.y;
    int e3 = e2 + v.z;
    int s  = e3 + v.w;

    int incl = s;
#pragma unroll
    for (int d = 1; d < 32; d <<= 1) {
        int u = __shfl_up_sync(0xffffffffu, incl, d);
        if ((t & 31) >= d) incl += u;
    }
    if ((t & 31) == 31) wsum[t >> 5] = incl;
    __syncthreads();

    if (t < 8) {
        int ws = wsum[t];
        int wincl = ws;
#pragma unroll
        for (int d = 1; d < 8; d <<= 1) {
            int u = __shfl_up_sync(0x000000ffu, wincl, d);
            if (t >= d) wincl += u;
        }
        wsum[t] = wincl - ws;
        if (t == 7) g_blocksum[blockIdx.x] = wincl;
    }
    __syncthreads();
    int wbase = wsum[t >> 5];

    const int base = wbase + (incl - s);
    if (i0 < N_NODES)
        *(int4*)(g_off + i0) = make_int4(base, base + e1, base + e2, base + e3);
}

__global__ __launch_bounds__(256) void scanC_kernel() {
    __shared__ int bs[SCAN_NBLK];
    const int t = threadIdx.x;
    if (t < SCAN_NBLK) bs[t] = g_blocksum[t];
    __syncthreads();

    int base = 0;
#pragma unroll 8
    for (int j = 0; j < SCAN_NBLK; j++)
        if (j < blockIdx.x) base += bs[j];

    const int i0 = blockIdx.x * SCAN_CHUNK + t * 4;
    if (i0 < N_NODES) {
        int4 v = *(const int4*)(g_off + i0);
        v.x += base; v.y += base; v.z += base; v.w += base;
        *(int4*)(g_off + i0)  = v;
        *(int4*)(g_woff + i0) = v;
    }
    if (blockIdx.x == 0 && t == 0) g_off[N_NODES] = N_EDGES;
}

__global__ void scatter_kernel(const int* __restrict__ src, const int* __restrict__ dst) {
    int e = blockIdx.x * blockDim.x + threadIdx.x;
    if (e < N_EDGES) {
        int d = dst[e];
        int p = atomicAdd(&g_woff[d], 1);
        g_srcs[p] = src[e];
    }
}

// ---------------- per-node fused attention + aggregation + projection ------
__device__ __forceinline__ float lrelu(float v) {
    return v > 0.f ? v : NEG_SLOPE * v;
}
// gather one xl row-slice (4 halves = 8B) and convert
__device__ __forceinline__ float4 gather_xl(int s, int l) {
    const uint2 u = *(const uint2*)(g_xl + (size_t)s * HC + 4 * l);
    float2 lo = __half22float2(*(const __half2*)&u.x);
    float2 hi = __half22float2(*(const __half2*)&u.y);
    return make_float4(lo.x, lo.y, hi.x, hi.y);
}

__global__ __launch_bounds__(256) void node_kernel(const float* __restrict__ att,
                                                   const float* __restrict__ bias,
                                                   const float* __restrict__ Wp,
                                                   const float* __restrict__ bp,
                                                   float* __restrict__ out) {
    __shared__ float Wpt[DIM_OUT][130];
    __shared__ float sbuf[8][HC];

    const int t = threadIdx.x;
    const int w = t >> 5;
    const int l = t & 31;

    for (int i = t; i < HC * DIM_OUT / 4; i += 256) {
        float4 v = ((const float4*)Wp)[i];
        int k = i >> 3;
        int o = (i & 7) * 4;
        Wpt[o + 0][k] = v.x;
        Wpt[o + 1][k] = v.y;
        Wpt[o + 2][k] = v.z;
        Wpt[o + 3][k] = v.w;
    }
    __syncthreads();

    const float4 a4  = *(const float4*)(att + l * 4);
    const float4 b4  = *(const float4*)(bias + l * 4);
    const float  bpl = bp[l];
    const int wg = blockIdx.x * 8 + w;

    for (int nn = 0; nn < 4; nn++) {
        const int node = wg * 4 + nn;
        if (node >= N_NODES) break;

        const float4 xr4 = *(const float4*)(g_xr + (size_t)node * HC + l * 4);
        const int e0 = g_off[node];
        const int e1 = g_off[node + 1];

        float denom = 0.f;
        float4 acc = make_float4(0.f, 0.f, 0.f, 0.f);

        for (int base = e0; base < e1; base += 32) {
            const int nE = min(32, e1 - base);
            int sv = 0;
            if (l < nE) sv = g_srcs[base + l];

            for (int j = 0; j < nE; j += 4) {
                const int s0 = __shfl_sync(0xffffffffu, sv, j);
                const int s1 = __shfl_sync(0xffffffffu, sv, (j + 1) & 31);
                const int s2 = __shfl_sync(0xffffffffu, sv, (j + 2) & 31);
                const int s3 = __shfl_sync(0xffffffffu, sv, (j + 3) & 31);
                const bool h1 = (j + 1) < nE, h2 = (j + 2) < nE, h3 = (j + 3) < nE;

                // 4 independent 8B gathers in flight
                const float4 x0 = gather_xl(s0, l);
                const float4 x1 = h1 ? gather_xl(s1, l) : make_float4(0.f, 0.f, 0.f, 0.f);
                const float4 x2 = h2 ? gather_xl(s2, l) : make_float4(0.f, 0.f, 0.f, 0.f);
                const float4 x3 = h3 ? gather_xl(s3, l) : make_float4(0.f, 0.f, 0.f, 0.f);

                float p0 = a4.x * lrelu(x0.x + xr4.x) + a4.y * lrelu(x0.y + xr4.y)
                         + a4.z * lrelu(x0.z + xr4.z) + a4.w * lrelu(x0.w + xr4.w);
                float p1 = a4.x * lrelu(x1.x + xr4.x) + a4.y * lrelu(x1.y + xr4.y)
                         + a4.z * lrelu(x1.z + xr4.z) + a4.w * lrelu(x1.w + xr4.w);
                float p2 = a4.x * lrelu(x2.x + xr4.x) + a4.y * lrelu(x2.y + xr4.y)
                         + a4.z * lrelu(x2.z + xr4.z) + a4.w * lrelu(x2.w + xr4.w);
                float p3 = a4.x * lrelu(x3.x + xr4.x) + a4.y * lrelu(x3.y + xr4.y)
                         + a4.z * lrelu(x3.z + xr4.z) + a4.w * lrelu(x3.w + xr4.w);

                // per-head 8-lane reductions, 4 chains interleaved
                p0 += __shfl_xor_sync(0xffffffffu, p0, 4);
                p1 += __shfl_xor_sync(0xffffffffu, p1, 4);
                p2 += __shfl_xor_sync(0xffffffffu, p2, 4);
                p3 += __shfl_xor_sync(0xffffffffu, p3, 4);
                p0 += __shfl_xor_sync(0xffffffffu, p0, 2);
                p1 += __shfl_xor_sync(0xffffffffu, p1, 2);
                p2 += __shfl_xor_sync(0xffffffffu, p2, 2);
                p3 += __shfl_xor_sync(0xffffffffu, p3, 2);
                p0 += __shfl_xor_sync(0xffffffffu, p0, 1);
                p1 += __shfl_xor_sync(0xffffffffu, p1, 1);
                p2 += __shfl_xor_sync(0xffffffffu, p2, 1);
                p3 += __shfl_xor_sync(0xffffffffu, p3, 1);

                const float ev0 = __expf(p0);
                const float ev1 = h1 ? __expf(p1) : 0.f;
                const float ev2 = h2 ? __expf(p2) : 0.f;
                const float ev3 = h3 ? __expf(p3) : 0.f;
                denom += (ev0 + ev1) + (ev2 + ev3);
                acc.x += x0.x * ev0 + x1.x * ev1 + x2.x * ev2 + x3.x * ev3;
                acc.y += x0.y * ev0 + x1.y * ev1 + x2.y * ev2 + x3.y * ev3;
                acc.z += x0.z * ev0 + x1.z * ev1 + x2.z * ev2 + x3.z * ev3;
                acc.w += x0.w * ev0 + x1.w * ev1 + x2.w * ev2 + x3.w * ev3;
            }
        }

        const float inv = 1.f / (denom + 1e-16f);
        sbuf[w][4 * l + 0] = acc.x * inv + b4.x;
        sbuf[w][4 * l + 1] = acc.y * inv + b4.y;
        sbuf[w][4 * l + 2] = acc.z * inv + b4.z;
        sbuf[w][4 * l + 3] = acc.w * inv + b4.w;
        __syncwarp();

        const u64* sp = (const u64*)&sbuf[w][0];
        const u64* wp = (const u64*)&Wpt[l][0];
        u64 r2 = pack2(bpl, 0.f);
#pragma unroll 8
        for (int k2 = 0; k2 < HC / 2; k2++) ffma2(r2, sp[k2], wp[k2]);
        float2 rr = unpack2(r2);
        out[(size_t)node * DIM_OUT + l] = rr.x + rr.y;
        __syncwarp();
    }
}

// ---------------- launch: two-stream fork/join inside the captured graph ----
extern "C" void kernel_launch(void* const* d_in, const int* in_sizes, int n_in,
                              void* d_out, int out_size) {
    const float* x    = (const float*)d_in[0];
    const int*   ei   = (const int*)d_in[1];
    const float* Wl   = (const float*)d_in[2];
    const float* Wr   = (const float*)d_in[3];
    const float* att  = (const float*)d_in[4];
    const float* bias = (const float*)d_in[5];
    const float* Wp   = (const float*)d_in[6];
    const float* bp   = (const float*)d_in[7];
    const int* src = ei;
    const int* dst = ei + N_EDGES;

    cudaFuncSetAttribute(gemm_tc, cudaFuncAttributeMaxDynamicSharedMemorySize, SM_TOTAL);

    // lazily created, reused every call (no device memory involved)
    static cudaStream_t s1 = nullptr;
    static cudaEvent_t evFork = nullptr, evJoin = nullptr;
    if (s1 == nullptr) {
        cudaStreamCreateWithFlags(&s1, cudaStreamNonBlocking);
        cudaEventCreateWithFlags(&evFork, cudaEventDisableTiming);
        cudaEventCreateWithFlags(&evJoin, cudaEventDisableTiming);
    }

    // fork: CSR-build branch on s1
    cudaEventRecord(evFork, 0);
    cudaStreamWaitEvent(s1, evFork, 0);
    zero_cnt_kernel<<<(N_NODES + 255) / 256, 256, 0, s1>>>();
    hist_kernel<<<(N_EDGES + 255) / 256, 256, 0, s1>>>(dst);
    scanA_kernel<<<SCAN_NBLK, 256, 0, s1>>>();
    scanC_kernel<<<SCAN_NBLK, 256, 0, s1>>>();
    scatter_kernel<<<(N_EDGES + 255) / 256, 256, 0, s1>>>(src, dst);
    cudaEventRecord(evJoin, s1);

    // main branch: GEMM
    prepB_kernel<<<64, 256>>>(Wl, Wr);
    gemm_tc<<<N_MTILES, 256, SM_TOTAL>>>(x);

    // join, then the fused node phase
    cudaStreamWaitEvent(0, evJoin, 0);
    node_kernel<<<(N_NODES + 31) / 32, 256>>>(att, bias, Wp, bp, (float*)d_out);
}